// round 1
// baseline (speedup 1.0000x reference)
#include <cuda_runtime.h>

#define BINS 32
#define NBATCH 64
#define REGIONS (NBATCH * 4)            // 256 regions: batch x quadrant
#define BPR 16                          // blocks per region
#define THREADS 256
#define F4_PER_REGION (3 * 256 * 64)    // 3 channels * 256 rows * 64 float4/row = 49152
#define F4_PER_BLOCK (F4_PER_REGION / BPR)   // 3072
#define ITERS (F4_PER_BLOCK / THREADS)       // 12
#define OUT_ELEMS (NBATCH * 96 * 16)         // 98304

__device__ int g_counts[REGIONS * BINS];

__global__ void zero_counts_kernel() {
    int i = blockIdx.x * blockDim.x + threadIdx.x;
    if (i < REGIONS * BINS) g_counts[i] = 0;
}

__device__ __forceinline__ void count_round(float x, unsigned neg0, unsigned neg1,
                                            unsigned neg2, unsigned neg3, unsigned neg4,
                                            unsigned& cnt) {
    // bin = clamp(floor(x*32), 0, 31); valid iff 0 <= x <= 1 (x==1 -> bin 31)
    int ib = __float2int_rd(x * 32.0f);
    ib = min(max(ib, 0), 31);
    bool valid = (x >= 0.0f) && (x <= 1.0f);
    unsigned V  = __ballot_sync(0xffffffffu, valid);
    unsigned b0 = __ballot_sync(0xffffffffu, ib & 1);
    unsigned b1 = __ballot_sync(0xffffffffu, (ib >> 1) & 1);
    unsigned b2 = __ballot_sync(0xffffffffu, (ib >> 2) & 1);
    unsigned b3 = __ballot_sync(0xffffffffu, (ib >> 3) & 1);
    unsigned b4 = __ballot_sync(0xffffffffu, (ib >> 4) & 1);
    // lane l counts elements whose bin == l
    unsigned m = V & (b0 ^ neg0) & (b1 ^ neg1) & (b2 ^ neg2) & (b3 ^ neg3) & (b4 ^ neg4);
    cnt += __popc(m);
}

__global__ __launch_bounds__(THREADS) void hist_kernel(const float4* __restrict__ in4) {
    const int region = blockIdx.x / BPR;
    const int chunk  = blockIdx.x % BPR;
    const int b  = region >> 2;
    const int qr = (region >> 1) & 1;
    const int qc = region & 1;
    const int lane = threadIdx.x & 31;

    // per-lane bit-select masks: negk = ((lane>>k)&1) ? 0 : ~0
    const unsigned neg0 = ((lane >> 0) & 1) ? 0u : 0xffffffffu;
    const unsigned neg1 = ((lane >> 1) & 1) ? 0u : 0xffffffffu;
    const unsigned neg2 = ((lane >> 2) & 1) ? 0u : 0xffffffffu;
    const unsigned neg3 = ((lane >> 3) & 1) ? 0u : 0xffffffffu;
    const unsigned neg4 = ((lane >> 4) & 1) ? 0u : 0xffffffffu;

    unsigned cnt = 0;
    const int f4base = chunk * F4_PER_BLOCK + threadIdx.x;

#pragma unroll
    for (int it = 0; it < ITERS; ++it) {
        int f4 = f4base + it * THREADS;       // flat float4 index within region
        int c   = f4 >> 14;                   // / 16384 (channel)
        int rem = f4 & 16383;
        int r   = rem >> 6;                   // row within quadrant (0..255)
        int c4  = rem & 63;                   // float4 col within quadrant (0..63)
        // global float4 index: ((b*3+c)*512*512 + (qr*256+r)*512 + qc*256 + c4*4) / 4
        int gidx = ((b * 3 + c) << 16) + ((qr * 256 + r) << 7) + (qc << 6) + c4;
        float4 v = __ldg(&in4[gidx]);
        count_round(v.x, neg0, neg1, neg2, neg3, neg4, cnt);
        count_round(v.y, neg0, neg1, neg2, neg3, neg4, cnt);
        count_round(v.z, neg0, neg1, neg2, neg3, neg4, cnt);
        count_round(v.w, neg0, neg1, neg2, neg3, neg4, cnt);
    }

    __shared__ int sh[BINS];
    if (threadIdx.x < BINS) sh[threadIdx.x] = 0;
    __syncthreads();
    atomicAdd(&sh[lane], (int)cnt);
    __syncthreads();
    if (threadIdx.x < BINS)
        atomicAdd(&g_counts[region * BINS + threadIdx.x], sh[threadIdx.x]);
}

__global__ void epilogue_kernel(float* __restrict__ out) {
    int i = blockIdx.x * blockDim.x + threadIdx.x;
    if (i >= OUT_ELEMS) return;
    int b   = i / (96 * 16);
    int rem = i % (96 * 16);
    int ch  = rem >> 4;          // 0..95
    int pix = rem & 15;          // 4x4 grid
    int gi = pix >> 2, gj = pix & 3;
    float v;
    if (ch < 32) {
        int bin  = ch;
        int base = b * 4;
        int tot = g_counts[(base + 0) * BINS + bin] + g_counts[(base + 1) * BINS + bin]
                + g_counts[(base + 2) * BINS + bin] + g_counts[(base + 3) * BINS + bin];
        v = (float)tot * (1.0f / 262144.0f);
    } else if (ch < 64) {
        int bin = ch - 32;
        int qr = gi >> 1, qc = gj >> 1;
        v = (float)g_counts[(b * 4 + qr * 2 + qc) * BINS + bin] * (1.0f / 65536.0f);
    } else {
        v = 0.0f;
    }
    out[i] = v;
}

extern "C" void kernel_launch(void* const* d_in, const int* in_sizes, int n_in,
                              void* d_out, int out_size) {
    (void)in_sizes; (void)n_in; (void)out_size;
    const float4* in4 = (const float4*)d_in[0];
    float* out = (float*)d_out;

    zero_counts_kernel<<<(REGIONS * BINS + 255) / 256, 256>>>();
    hist_kernel<<<REGIONS * BPR, THREADS>>>(in4);
    epilogue_kernel<<<(OUT_ELEMS + 255) / 256, 256>>>(out);
}

// round 3
// speedup vs baseline: 1.0402x; 1.0402x over previous
#include <cuda_runtime.h>

#define BINS 32
#define NBATCH 64
#define REGIONS (NBATCH * 4)                 // batch x quadrant
#define BPR 16                               // chunks (blocks) per region
#define THREADS 256
#define F4_PER_REGION (3 * 256 * 64)         // 49152 float4 per region
#define F4_PER_BLOCK (F4_PER_REGION / BPR)   // 3072
#define LOADS (F4_PER_BLOCK / THREADS)       // 12 float4 per thread
#define BATCH 4                              // float4 per pipeline batch
#define NBATCHES (LOADS / BATCH)             // 3
#define OUT_ELEMS (NBATCH * 96 * 16)

// Per-(region,chunk) partial counts. Fully overwritten every call -> no zeroing.
__device__ int g_partial[REGIONS * BPR * BINS];

__device__ __forceinline__ void count_round(float x, unsigned neg0, unsigned neg1,
                                            unsigned neg2, unsigned neg3, unsigned neg4,
                                            unsigned& cnt) {
    // t = floor(x*32) for x in [0,1) via exact fma_rz bit-trick:
    // x*32 is exact (power-of-2 scale); +2^23 then round-toward-zero == floor.
    float f = __fmaf_rz(x, 32.0f, 8388608.0f);
    int t = __float_as_int(f) - 0x4B000000;
    // x == 1.0 exactly -> t == 32, valid, bin 31. x>1 -> t>=33 (or huge). x<0 -> t<0.
    int ib = (x == 1.0f) ? 31 : t;
    bool valid = ((unsigned)ib) <= 31u;
    unsigned V  = __ballot_sync(0xffffffffu, valid);
    unsigned b0 = __ballot_sync(0xffffffffu, ib & 1);
    unsigned b1 = __ballot_sync(0xffffffffu, ib & 2);
    unsigned b2 = __ballot_sync(0xffffffffu, ib & 4);
    unsigned b3 = __ballot_sync(0xffffffffu, ib & 8);
    unsigned b4 = __ballot_sync(0xffffffffu, ib & 16);
    unsigned m = V & (b0 ^ neg0) & (b1 ^ neg1) & (b2 ^ neg2) & (b3 ^ neg3) & (b4 ^ neg4);
    cnt += __popc(m);
}

__global__ __launch_bounds__(THREADS) void hist_kernel(const float4* __restrict__ in4) {
    const int region = blockIdx.x / BPR;
    const int chunk  = blockIdx.x % BPR;
    const int b  = region >> 2;
    const int qr = (region >> 1) & 1;
    const int qc = region & 1;
    const int lane = threadIdx.x & 31;

    const unsigned neg0 = (lane & 1)  ? 0u : 0xffffffffu;
    const unsigned neg1 = (lane & 2)  ? 0u : 0xffffffffu;
    const unsigned neg2 = (lane & 4)  ? 0u : 0xffffffffu;
    const unsigned neg3 = (lane & 8)  ? 0u : 0xffffffffu;
    const unsigned neg4 = (lane & 16) ? 0u : 0xffffffffu;

    const int f4_0 = chunk * F4_PER_BLOCK + threadIdx.x;
    const int gbase = ((b * 3) << 16) + (qr << 15) + (qc << 6);  // batch/quadrant base

    // address for the k-th float4 of this thread
    auto gidx_of = [&](int k) -> int {
        int f4  = f4_0 + k * THREADS;              // flat index within region
        int c   = f4 >> 14;                        // channel 0..2
        int rem = f4 & 16383;
        int r   = rem >> 6;                        // row in quadrant 0..255
        int c4  = rem & 63;                        // float4 col 0..63
        return gbase + (c << 16) + (r << 7) + c4;
    };

    unsigned cnt = 0;
    float4 cur[BATCH], nxt[BATCH];

#pragma unroll
    for (int j = 0; j < BATCH; ++j) cur[j] = __ldg(&in4[gidx_of(j)]);

#pragma unroll
    for (int bt = 0; bt < NBATCHES; ++bt) {
        if (bt + 1 < NBATCHES) {
#pragma unroll
            for (int j = 0; j < BATCH; ++j)
                nxt[j] = __ldg(&in4[gidx_of((bt + 1) * BATCH + j)]);
        }
#pragma unroll
        for (int j = 0; j < BATCH; ++j) {
            count_round(cur[j].x, neg0, neg1, neg2, neg3, neg4, cnt);
            count_round(cur[j].y, neg0, neg1, neg2, neg3, neg4, cnt);
            count_round(cur[j].z, neg0, neg1, neg2, neg3, neg4, cnt);
            count_round(cur[j].w, neg0, neg1, neg2, neg3, neg4, cnt);
        }
#pragma unroll
        for (int j = 0; j < BATCH; ++j) cur[j] = nxt[j];
    }

    __shared__ int sh[BINS];
    if (threadIdx.x < BINS) sh[threadIdx.x] = 0;
    __syncthreads();
    atomicAdd(&sh[lane], (int)cnt);
    __syncthreads();
    if (threadIdx.x < BINS)
        g_partial[(region * BPR + chunk) * BINS + threadIdx.x] = sh[threadIdx.x];
}

__global__ __launch_bounds__(128) void epilogue_kernel(float* __restrict__ out) {
    const int b   = blockIdx.x;
    const int q   = threadIdx.x >> 5;   // quadrant 0..3
    const int bin = threadIdx.x & 31;

    int s = 0;
    const int* p = &g_partial[((b * 4 + q) * BPR) * BINS + bin];
#pragma unroll
    for (int k = 0; k < BPR; ++k) s += p[k * BINS];

    __shared__ int sq[4][BINS];
    sq[q][bin] = s;
    __syncthreads();

    float* ob = out + b * 96 * 16;
    if (q == 0) {
        int tot = sq[0][bin] + sq[1][bin] + sq[2][bin] + sq[3][bin];
        float v0 = (float)tot * (1.0f / 262144.0f);
#pragma unroll
        for (int pix = 0; pix < 16; ++pix) ob[bin * 16 + pix] = v0;
    } else if (q == 1) {
#pragma unroll
        for (int pix = 0; pix < 16; ++pix) {
            int gi = pix >> 2, gj = pix & 3;
            ob[(32 + bin) * 16 + pix] =
                (float)sq[(gi >> 1) * 2 + (gj >> 1)][bin] * (1.0f / 65536.0f);
        }
    } else if (q == 2) {
#pragma unroll
        for (int pix = 0; pix < 16; ++pix) ob[(64 + bin) * 16 + pix] = 0.0f;
    }
}

extern "C" void kernel_launch(void* const* d_in, const int* in_sizes, int n_in,
                              void* d_out, int out_size) {
    (void)in_sizes; (void)n_in; (void)out_size;
    const float4* in4 = (const float4*)d_in[0];
    float* out = (float*)d_out;

    hist_kernel<<<REGIONS * BPR, THREADS>>>(in4);
    epilogue_kernel<<<NBATCH, 128>>>(out);
}

// round 4
// speedup vs baseline: 2.2397x; 2.1530x over previous
#include <cuda_runtime.h>

#define BINS 32
#define NBATCH 64
#define REGIONS 256                     // batch x quadrant
#define CQB 6                           // per region: 3 channels * 2 row-halves
#define NBLOCKS (REGIONS * CQB)         // 1536
#define THREADS 256
#define ITERS 8                         // 8 groups of 16 elements = 32 float4/thread

__device__ int g_partial[NBLOCKS * BINS];

__device__ __forceinline__ void csa(unsigned& s, unsigned& c,
                                    unsigned a, unsigned b, unsigned d) {
    s = a ^ b ^ d;                      // 1 LOP3
    c = (a & b) | (a & d) | (b & d);    // 1 LOP3 (MAJ)
}

// Sum 16 one-hot words into 5 bit-planes (weights 1,2,4,8,16), per bit-column.
__device__ __forceinline__ void compress16(const unsigned h[16], unsigned g[5]) {
    unsigned s0,c0,s1,c1,s2,c2,s3,c3,s4,c4;
    csa(s0,c0,h[0],h[1],h[2]);
    csa(s1,c1,h[3],h[4],h[5]);
    csa(s2,c2,h[6],h[7],h[8]);
    csa(s3,c3,h[9],h[10],h[11]);
    csa(s4,c4,h[12],h[13],h[14]);
    unsigned s5,c5,s6,c6;
    csa(s5,c5,s0,s1,s2);
    csa(s6,c6,s3,s4,h[15]);
    unsigned c7 = s5 & s6;
    g[0] = s5 ^ s6;
    // weight-2 pool: c0..c7
    unsigned s7,d0,s8,d1,s9,d2;
    csa(s7,d0,c0,c1,c2);
    csa(s8,d1,c3,c4,c5);
    csa(s9,d2,s7,s8,c6);
    unsigned d3 = s9 & c7;
    g[1] = s9 ^ c7;
    // weight-4 pool: d0..d3
    unsigned s10,e0;
    csa(s10,e0,d0,d1,d2);
    unsigned e1 = s10 & d3;
    g[2] = s10 ^ d3;
    // weight-8 pool: e0,e1
    g[3] = e0 ^ e1;
    g[4] = e0 & e1;                     // weight-16
}

// acc (8 planes) += g (5 planes), bitwise ripple-carry per column.
__device__ __forceinline__ void acc_add(unsigned a[8], const unsigned g[5]) {
    unsigned c = a[0] & g[0]; a[0] ^= g[0];
#pragma unroll
    for (int j = 1; j < 5; ++j) {
        unsigned s = a[j] ^ g[j];
        unsigned nc = (a[j] & g[j]) | (c & s);  // maj(a,g,c)
        a[j] = s ^ c;
        c = nc;
    }
    unsigned nc = a[5] & c; a[5] ^= c; c = nc;
    nc = a[6] & c; a[6] ^= c; c = nc;
    a[7] ^= c;
}

// One stage of Hacker's-Delight 32x32 bit transpose (warp-distributed).
__device__ __forceinline__ unsigned xpose_step(unsigned x, int lane, int j, unsigned m) {
    unsigned y = __shfl_xor_sync(0xffffffffu, x, j);
    bool lo = (lane & j) == 0;
    unsigned a = lo ? x : y;
    unsigned b = lo ? y : x;
    unsigned t = (a ^ (b >> j)) & m;
    return x ^ (lo ? t : (t << j));
}

__device__ __forceinline__ unsigned onehot(float x) {
    // x in [0,1): floor(x*32) sits in the low 5 bits of the fp word after +2^23 (RZ).
    int t = __float_as_int(__fmaf_rz(x, 32.0f, 8388608.0f));
    return 1u << (t & 31);
}

__global__ __launch_bounds__(THREADS) void hist_kernel(const float4* __restrict__ in4) {
    const int blk    = blockIdx.x;
    const int region = blk / CQB;
    const int sub    = blk % CQB;       // ch*2 + half
    const int ch   = sub >> 1;
    const int half = sub & 1;
    const int b  = region >> 2;
    const int qr = (region >> 1) & 1;
    const int qc = region & 1;
    const int tid  = threadIdx.x;
    const int lane = tid & 31;

    // float4 base: image (b,ch), quadrant row qr*256 + half*128 + (tid>>6), col qc*256 + (tid&63)*4
    const int base = ((b * 3 + ch) << 16) + (qr << 15) + (half << 14)
                   + ((tid >> 6) << 7) + (qc << 6) + (tid & 63);

    unsigned acc[8];
#pragma unroll
    for (int j = 0; j < 8; ++j) acc[j] = 0u;

#pragma unroll
    for (int it = 0; it < ITERS; ++it) {
        unsigned h[16];
#pragma unroll
        for (int j = 0; j < 4; ++j) {
            // k = it*4 + j; each k advances 4 rows = 512 float4. Constant offsets.
            float4 v = __ldg(&in4[base + (it * 4 + j) * 512]);
            h[j * 4 + 0] = onehot(v.x);
            h[j * 4 + 1] = onehot(v.y);
            h[j * 4 + 2] = onehot(v.z);
            h[j * 4 + 3] = onehot(v.w);
        }
        unsigned g[5];
        compress16(h, g);
        acc_add(acc, g);
    }

    // Transpose each plane: after HD transpose (msb convention), lane r's word
    // collects, over all lanes, their count-bit for bin (31-r).
#pragma unroll
    for (int j = 0; j < 8; ++j) {
        unsigned x = acc[j];
        x = xpose_step(x, lane, 16, 0x0000FFFFu);
        x = xpose_step(x, lane,  8, 0x00FF00FFu);
        x = xpose_step(x, lane,  4, 0x0F0F0F0Fu);
        x = xpose_step(x, lane,  2, 0x33333333u);
        x = xpose_step(x, lane,  1, 0x55555555u);
        acc[j] = x;
    }
    unsigned cnt = 0;
#pragma unroll
    for (int j = 0; j < 8; ++j) cnt += __popc(acc[j]) << j;

    __shared__ int sh[BINS];
    if (tid < BINS) sh[tid] = 0;
    __syncthreads();
    atomicAdd(&sh[31 - lane], (int)cnt);
    __syncthreads();
    if (tid < BINS)
        g_partial[blk * BINS + tid] = sh[tid];
}

__global__ __launch_bounds__(128) void epilogue_kernel(float* __restrict__ out) {
    const int b   = blockIdx.x;
    const int q   = threadIdx.x >> 5;   // quadrant 0..3
    const int bin = threadIdx.x & 31;

    const int region = b * 4 + q;
    int s = 0;
#pragma unroll
    for (int i = 0; i < CQB; ++i)
        s += g_partial[(region * CQB + i) * BINS + bin];

    __shared__ int sq[4][BINS];
    sq[q][bin] = s;
    __syncthreads();

    float* ob = out + b * 96 * 16;
    if (q == 0) {
        int tot = sq[0][bin] + sq[1][bin] + sq[2][bin] + sq[3][bin];
        float v0 = (float)tot * (1.0f / 262144.0f);
#pragma unroll
        for (int pix = 0; pix < 16; ++pix) ob[bin * 16 + pix] = v0;
    } else if (q == 1) {
#pragma unroll
        for (int pix = 0; pix < 16; ++pix) {
            int gi = pix >> 2, gj = pix & 3;
            ob[(32 + bin) * 16 + pix] =
                (float)sq[(gi >> 1) * 2 + (gj >> 1)][bin] * (1.0f / 65536.0f);
        }
    } else if (q == 2) {
#pragma unroll
        for (int pix = 0; pix < 16; ++pix) ob[(64 + bin) * 16 + pix] = 0.0f;
    }
}

extern "C" void kernel_launch(void* const* d_in, const int* in_sizes, int n_in,
                              void* d_out, int out_size) {
    (void)in_sizes; (void)n_in; (void)out_size;
    const float4* in4 = (const float4*)d_in[0];
    float* out = (float*)d_out;

    hist_kernel<<<NBLOCKS, THREADS>>>(in4);
    epilogue_kernel<<<NBATCH, 128>>>(out);
}